// round 1
// baseline (speedup 1.0000x reference)
#include <cuda_runtime.h>
#include <cstdint>

#define CIN   32
#define COUT  64
#define KVOL  4
#define KSTRIDE (CIN * COUT + 8)   // 2056 floats: +8 pad shifts each k to a new bank group
#define EPS   1e-4f
#define LEAK  0.333f

#define STATS_BLOCKS 1184          // 148 SMs * 8

__device__ float g_partials[STATS_BLOCKS * 128];  // [block][0:64 sum, 64:128 sumsq]
__device__ float g_coef[128];                     // [0:64 A, 64:128 B]

// ---- packed f32x2 helpers (sm_103a) ---------------------------------------
__device__ __forceinline__ unsigned long long pack2(float x) {
    unsigned long long r;
    asm("mov.b64 %0, {%1, %1};" : "=l"(r) : "f"(x));
    return r;
}
__device__ __forceinline__ unsigned long long ffma2(unsigned long long a,
                                                    unsigned long long b,
                                                    unsigned long long c) {
    unsigned long long d;
    asm("fma.rn.f32x2 %0, %1, %2, %3;" : "=l"(d) : "l"(a), "l"(b), "l"(c));
    return d;
}
__device__ __forceinline__ void unpack2(unsigned long long v, float& lo, float& hi) {
    asm("mov.b64 {%0, %1}, %2;" : "=f"(lo), "=f"(hi) : "l"(v));
}

// ---- kernel 1: gather-GEMV-scatter conv ------------------------------------
__global__ __launch_bounds__(256, 2) void conv_scatter(
    const float* __restrict__ feat,
    const float* __restrict__ weight,
    const int*   __restrict__ out_idx,
    const int*   __restrict__ kern_idx,
    float*       __restrict__ out,
    int n_rows)
{
    __shared__ float wsh[KVOL * KSTRIDE];
    for (int t = threadIdx.x; t < KVOL * CIN * COUT; t += blockDim.x) {
        int k = t >> 11;          // / 2048
        int r = t & 2047;
        wsh[k * KSTRIDE + r] = weight[t];
    }
    __syncthreads();

    int stride = gridDim.x * blockDim.x;
    for (int i = blockIdx.x * blockDim.x + threadIdx.x; i < n_rows; i += stride) {
        int k = kern_idx[i];
        int o = out_idx[i];
        const float4* fp = reinterpret_cast<const float4*>(feat + (size_t)i * CIN);
        const char*   wb = reinterpret_cast<const char*>(wsh + k * KSTRIDE);

        unsigned long long acc[32];
        #pragma unroll
        for (int c = 0; c < 32; c++) acc[c] = 0ull;

        #pragma unroll 2
        for (int jg = 0; jg < CIN / 4; jg++) {
            float4 f4 = fp[jg];
            float fv[4] = {f4.x, f4.y, f4.z, f4.w};
            #pragma unroll
            for (int jj = 0; jj < 4; jj++) {
                int j = jg * 4 + jj;
                unsigned long long f2 = pack2(fv[jj]);
                const ulonglong2* wr =
                    reinterpret_cast<const ulonglong2*>(wb + (size_t)j * COUT * 4);
                #pragma unroll
                for (int c8 = 0; c8 < 16; c8++) {
                    ulonglong2 w = wr[c8];
                    acc[c8 * 2 + 0] = ffma2(w.x, f2, acc[c8 * 2 + 0]);
                    acc[c8 * 2 + 1] = ffma2(w.y, f2, acc[c8 * 2 + 1]);
                }
            }
        }

        float4* orow = reinterpret_cast<float4*>(out + (size_t)o * COUT);
        #pragma unroll
        for (int q = 0; q < 16; q++) {
            float4 v;
            unpack2(acc[2 * q + 0], v.x, v.y);
            unpack2(acc[2 * q + 1], v.z, v.w);
            atomicAdd(&orow[q], v);   // sm_90+ vector RED, 16B aligned (row stride 256B)
        }
    }
}

// ---- kernel 2: per-channel sum / sumsq partials ----------------------------
__global__ __launch_bounds__(256) void stats_kernel(const float* __restrict__ out,
                                                    int n_out)
{
    __shared__ float sh[128];
    if (threadIdx.x < 128) sh[threadIdx.x] = 0.f;
    __syncthreads();

    int gid = blockIdx.x * blockDim.x + threadIdx.x;
    int c4 = threadIdx.x & 15;                 // fixed float4-column per thread
    int row0 = gid >> 4;
    int rstride = (gridDim.x * blockDim.x) >> 4;
    const float4* o4 = reinterpret_cast<const float4*>(out);

    float4 s = make_float4(0.f, 0.f, 0.f, 0.f);
    float4 q = make_float4(0.f, 0.f, 0.f, 0.f);
    for (int r = row0; r < n_out; r += rstride) {
        float4 v = o4[(size_t)r * 16 + c4];
        s.x += v.x; s.y += v.y; s.z += v.z; s.w += v.w;
        q.x += v.x * v.x; q.y += v.y * v.y; q.z += v.z * v.z; q.w += v.w * v.w;
    }
    // lanes l and l+16 share c4 -> fold
    s.x += __shfl_down_sync(0xFFFFFFFFu, s.x, 16);
    s.y += __shfl_down_sync(0xFFFFFFFFu, s.y, 16);
    s.z += __shfl_down_sync(0xFFFFFFFFu, s.z, 16);
    s.w += __shfl_down_sync(0xFFFFFFFFu, s.w, 16);
    q.x += __shfl_down_sync(0xFFFFFFFFu, q.x, 16);
    q.y += __shfl_down_sync(0xFFFFFFFFu, q.y, 16);
    q.z += __shfl_down_sync(0xFFFFFFFFu, q.z, 16);
    q.w += __shfl_down_sync(0xFFFFFFFFu, q.w, 16);

    if ((threadIdx.x & 31) < 16) {
        atomicAdd(&sh[c4 * 4 + 0], s.x);
        atomicAdd(&sh[c4 * 4 + 1], s.y);
        atomicAdd(&sh[c4 * 4 + 2], s.z);
        atomicAdd(&sh[c4 * 4 + 3], s.w);
        atomicAdd(&sh[64 + c4 * 4 + 0], q.x);
        atomicAdd(&sh[64 + c4 * 4 + 1], q.y);
        atomicAdd(&sh[64 + c4 * 4 + 2], q.z);
        atomicAdd(&sh[64 + c4 * 4 + 3], q.w);
    }
    __syncthreads();
    if (threadIdx.x < 128)
        g_partials[blockIdx.x * 128 + threadIdx.x] = sh[threadIdx.x];
}

// ---- kernel 3: reduce partials -> per-channel A,B coefficients -------------
__global__ void coef_kernel(const float* __restrict__ gamma,
                            const float* __restrict__ beta,
                            int n_out)
{
    int t = threadIdx.x;   // 0..127
    float acc = 0.f;
    for (int b = 0; b < STATS_BLOCKS; b++)
        acc += g_partials[b * 128 + t];
    __shared__ float tot[128];
    tot[t] = acc;
    __syncthreads();
    if (t < 64) {
        float inv_n = 1.0f / (float)n_out;
        float mean = tot[t] * inv_n;
        float var  = tot[64 + t] * inv_n - mean * mean;
        float A = gamma[t] * rsqrtf(var + EPS);
        float B = beta[t] - mean * A;
        g_coef[t] = A;
        g_coef[64 + t] = B;
    }
}

// ---- kernel 4: normalize + leaky relu (in place) ---------------------------
__global__ __launch_bounds__(256) void norm_kernel(float* __restrict__ out, int n_out)
{
    int gid = blockIdx.x * blockDim.x + threadIdx.x;
    int c4 = threadIdx.x & 15;
    const float4* cf = reinterpret_cast<const float4*>(g_coef);
    float4 A = cf[c4];
    float4 B = cf[16 + c4];
    int row0 = gid >> 4;
    int rstride = (gridDim.x * blockDim.x) >> 4;
    float4* o4 = reinterpret_cast<float4*>(out);
    for (int r = row0; r < n_out; r += rstride) {
        size_t idx = (size_t)r * 16 + c4;
        float4 v = o4[idx];
        float4 y;
        y.x = fmaf(v.x, A.x, B.x);
        y.y = fmaf(v.y, A.y, B.y);
        y.z = fmaf(v.z, A.z, B.z);
        y.w = fmaf(v.w, A.w, B.w);
        y.x = fmaxf(y.x, LEAK * y.x);   // == leaky_relu for 0<LEAK<1
        y.y = fmaxf(y.y, LEAK * y.y);
        y.z = fmaxf(y.z, LEAK * y.z);
        y.w = fmaxf(y.w, LEAK * y.w);
        o4[idx] = y;
    }
}

// ---- launch ----------------------------------------------------------------
extern "C" void kernel_launch(void* const* d_in, const int* in_sizes, int n_in,
                              void* d_out, int out_size)
{
    const float* feat    = (const float*)d_in[0];
    const float* weight  = (const float*)d_in[1];
    // d_in[2] = bias: mathematically cancelled by BN mean subtraction
    const float* gamma   = (const float*)d_in[3];
    const float* beta    = (const float*)d_in[4];
    const int*   out_idx = (const int*)d_in[5];
    const int*   kern_idx= (const int*)d_in[6];
    int n_rows = in_sizes[0] / CIN;
    int n_out  = out_size / COUT;
    float* out = (float*)d_out;

    cudaMemsetAsync(d_out, 0, (size_t)out_size * sizeof(float));
    conv_scatter<<<592, 256>>>(feat, weight, out_idx, kern_idx, out, n_rows);
    stats_kernel<<<STATS_BLOCKS, 256>>>(out, n_out);
    coef_kernel<<<1, 128>>>(gamma, beta, n_out);
    norm_kernel<<<1184, 256>>>(out, n_out);
}